// round 15
// baseline (speedup 1.0000x reference)
#include <cuda_runtime.h>
#include <math.h>

#define LRW 256
#define LRH 256
#define HRW 1024
#define HRH 1024
#define NC 3
#define RAD 4

#define LRN (NC * LRH * LRW)
#define SC (255.0f / 1023.0f)

// Scratch (no cudaMalloc allowed) — device globals.
__device__ float g_A[LRN];
__device__ float g_B[LRN];

// ---------------------------------------------------------------------------
// Helpers
// ---------------------------------------------------------------------------
__device__ __forceinline__ void load12(float* v, const float* base) {
    float4 q0 = *reinterpret_cast<const float4*>(base);
    float4 q1 = *reinterpret_cast<const float4*>(base + 4);
    float4 q2 = *reinterpret_cast<const float4*>(base + 8);
    v[0]=q0.x; v[1]=q0.y; v[2]=q0.z;  v[3]=q0.w;
    v[4]=q1.x; v[5]=q1.y; v[6]=q1.z;  v[7]=q1.w;
    v[8]=q2.x; v[9]=q2.y; v[10]=q2.z; v[11]=q2.w;
}

// h[i] = sum v[i..i+4], i = 0..7  (sliding 5-window)
__device__ __forceinline__ void hsum5(float* h, const float* v) {
    h[0] = v[0] + v[1] + v[2] + v[3] + v[4];
#pragma unroll
    for (int i = 1; i < 8; ++i) h[i] = h[i - 1] - v[i - 1] + v[i + 4];
}

// ---------------------------------------------------------------------------
// Fused low-res kernel: tile 16x16 per block (grid 16x16x3), 256 threads.
// (round-14 version, unchanged)
// ---------------------------------------------------------------------------
#define LTS 16
#define LEX 24
#define LSP 28

__global__ void __launch_bounds__(256) lr_fused(const float* __restrict__ lrx,
                                                const float* __restrict__ lry,
                                                const float* __restrict__ boxw) {
    __shared__ __align__(16) float Xs[LEX * LSP];
    __shared__ __align__(16) float Ys[LEX * LSP];
    __shared__ __align__(16) float Vx[LTS * LSP];
    __shared__ __align__(16) float Vy[LTS * LSP];
    __shared__ __align__(16) float Vxy[LTS * LSP];
    __shared__ __align__(16) float Vxx[LTS * LSP];

    const int c = blockIdx.z;
    const int x0t = blockIdx.x * LTS;
    const int y0t = blockIdx.y * LTS;
    const int tid = threadIdx.x;
    const float* __restrict__ px = lrx + c * LRH * LRW;
    const float* __restrict__ py = lry + c * LRH * LRW;

    for (int j = tid; j < LEX * LEX; j += 256) {
        int ly = j / LEX, lx = j % LEX;
        int Y = y0t - RAD + ly; Y = Y < 0 ? 0 : (Y > LRH - 1 ? LRH - 1 : Y);
        int X = x0t - RAD + lx; X = X < 0 ? 0 : (X > LRW - 1 ? LRW - 1 : X);
        Xs[ly * LSP + lx] = px[Y * LRW + X];
        Ys[ly * LSP + lx] = py[Y * LRW + X];
    }
    __syncthreads();

    for (int j = tid; j < LTS * LEX; j += 256) {
        int ry = j / LEX, lx = j % LEX;
        float sx = 0.f, sy = 0.f, sxy = 0.f, sxx = 0.f;
#pragma unroll
        for (int k = 0; k < 9; ++k) {
            float vx = Xs[(ry + k) * LSP + lx];
            float vy = Ys[(ry + k) * LSP + lx];
            sx += vx; sy += vy; sxy += vx * vy; sxx += vx * vx;
        }
        Vx[ry * LSP + lx] = sx;  Vy[ry * LSP + lx] = sy;
        Vxy[ry * LSP + lx] = sxy; Vxx[ry * LSP + lx] = sxx;
    }
    __syncthreads();

    if (tid < 64) {
        const int ty = tid >> 2;            // 0..15
        const int x0 = (tid & 3) << 2;      // 0,4,8,12
        float vx[12], vy[12], vxy[12], vxx[12];
        load12(vx,  &Vx[ty * LSP + x0]);
        load12(vy,  &Vy[ty * LSP + x0]);
        load12(vxy, &Vxy[ty * LSP + x0]);
        load12(vxx, &Vxx[ty * LSP + x0]);

        float hx[4], hy[4], hxy[4], hxx[4];
        hx[0] = vx[0]+vx[1]+vx[2]+vx[3]+vx[4]+vx[5]+vx[6]+vx[7]+vx[8];
        hy[0] = vy[0]+vy[1]+vy[2]+vy[3]+vy[4]+vy[5]+vy[6]+vy[7]+vy[8];
        hxy[0]= vxy[0]+vxy[1]+vxy[2]+vxy[3]+vxy[4]+vxy[5]+vxy[6]+vxy[7]+vxy[8];
        hxx[0]= vxx[0]+vxx[1]+vxx[2]+vxx[3]+vxx[4]+vxx[5]+vxx[6]+vxx[7]+vxx[8];
#pragma unroll
        for (int i = 1; i < 4; ++i) {
            hx[i]  = hx[i-1]  - vx[i-1]  + vx[i+8];
            hy[i]  = hy[i-1]  - vy[i-1]  + vy[i+8];
            hxy[i] = hxy[i-1] - vxy[i-1] + vxy[i+8];
            hxx[i] = hxx[i-1] - vxx[i-1] + vxx[i+8];
        }

        const float w = boxw[c * 81];
        float A_[4], B_[4];
#pragma unroll
        for (int p = 0; p < 4; ++p) {
            float mx = hx[p] * w, my = hy[p] * w, mxy = hxy[p] * w, mxx = hxx[p] * w;
            float A = (mxy - mx * my) / (mxx - mx * mx + 2.0f);   // EPS = 2
            A_[p] = A; B_[p] = my - A * mx;
        }
        int o = c * LRH * LRW + (y0t + ty) * LRW + (x0t + x0);
        *reinterpret_cast<float4*>(&g_A[o]) = make_float4(A_[0], A_[1], A_[2], A_[3]);
        *reinterpret_cast<float4*>(&g_B[o]) = make_float4(B_[0], B_[1], B_[2], B_[3]);
    }
}

// ---------------------------------------------------------------------------
// HR fused: block = 128-col x 16-row tile (grid 8x64x3), NOW 512 threads,
// __launch_bounds__(512,2): 64-reg cap -> 2 CTAs = 32 warps/SM (was 24).
// Phase 3: ONE row of 4 px per thread with EAGER P-FOLDING: each S/U row's
// hA/hB sums are immediately collapsed into P = fma(hA, im, hB), halving
// persistent register state (no pairing; LSU has headroom, occupancy not).
// Phases W/F0/F2 logic identical to round 13 (strides adapted).
// ---------------------------------------------------------------------------
#define XT 128
#define YS 16
#define SMP 140          // smem row stride (floats); 136 used
#define SR 20            // S rows: r in [Y0, Y0+19]
#define UR 16
#define EXR 24           // extended rows walked by F2
#define UOFF (2 * SR * SMP)
#define ABR 10           // staged A/B LR rows
#define ABC 36           // staged A/B LR cols
#define ABP 37           // stride
#define PCOLS 136        // padded HR cols per block
#define HTHREADS 512

// load S row pair (A,B) at given smem offsets; fold into P{l,r,c}[4]
__device__ __forceinline__ void fold_row(const float* baseA, const float* baseB,
                                         const float* imv,
                                         float* Pl, float* Pr, float* Pc) {
    float vA[12], hA[8], vB[12], hB[8];
    load12(vA, baseA); hsum5(hA, vA);
    load12(vB, baseB); hsum5(hB, vB);
#pragma unroll
    for (int p = 0; p < 4; ++p) {
        Pl[p] = fmaf(hA[p],     imv[p], hB[p]);
        Pr[p] = fmaf(hA[p + 4], imv[p], hB[p + 4]);
        Pc[p] = fmaf(vA[p + 4], imv[p], vB[p + 4]);
    }
}

__global__ void __launch_bounds__(HTHREADS, 2) hr_fused(const float* __restrict__ hrx,
                                                        float* __restrict__ out) {
    __shared__ __align__(16) float sm[(2 * SR + 2 * UR) * SMP];   // 40.3 KB
    __shared__ __align__(16) float sAB[2 * ABR * ABP];            // 2.96 KB
    __shared__ int   s_ek[EXR];      // HL-row index rel. jbase per ext row
    __shared__ float s_efy[EXR];     // vertical lerp fraction per ext row
    __shared__ int   s_cix[PCOLS];   // LR col rel. ixbase per padded col
    __shared__ float s_cfx[PCOLS];   // horizontal lerp fraction per padded col

    const int c  = blockIdx.z;
    const int X0 = blockIdx.x * XT;
    const int Y0 = blockIdx.y * YS;
    const int tid = threadIdx.x;

    // block-uniform base LR row / col
    int Yb = Y0 - 4; Yb = Yb < 0 ? 0 : Yb;
    int jbase = (int)floorf((float)Yb * SC);
    if (jbase > LRH - 2) jbase = LRH - 2;
    int Xb = X0 - 4; Xb = Xb < 0 ? 0 : Xb;
    int ixbase = (int)floorf((float)Xb * SC);
    if (ixbase > LRW - 2) ixbase = LRW - 2;

    // ---- thread's mapping: one row of 4 px ----
    const int row = tid >> 5;            // 0..15
    const int xl  = (tid & 31) << 2;     // 0..124

    // ---- Prefetch hrx (latency hidden behind W/F0/F2) ----
    const float4 im4 = *reinterpret_cast<const float4*>(
        &hrx[(c * HRH + Y0 + row) * HRW + X0 + xl]);

    // ---- Phase W: ext-row table + column table ----
    if (tid < EXR) {
        int Y = Y0 - 4 + tid; Y = Y < 0 ? 0 : (Y > HRH - 1 ? HRH - 1 : Y);
        float tt = (float)Y * SC;
        int iy = (int)floorf(tt); if (iy > LRH - 2) iy = LRH - 2;
        s_ek[tid]  = iy - jbase;
        s_efy[tid] = tt - (float)iy;
    } else if (tid >= 32 && tid < 32 + PCOLS) {
        int lx = tid - 32;
        int X = X0 - 4 + lx; X = X < 0 ? 0 : (X > HRW - 1 ? HRW - 1 : X);
        float tt = (float)X * SC;
        int ix = (int)floorf(tt); if (ix > LRW - 2) ix = LRW - 2;
        s_cix[lx] = ix - ixbase;           // 0..34; +1 <= 35 < ABC
        s_cfx[lx] = tt - (float)ix;
    }

    // ---- Phase F0: stage raw A,B sub-tile (coalesced scalar loads) ----
    for (int it = tid; it < 2 * ABR * ABC; it += HTHREADS) {
        int f   = it / (ABR * ABC);
        int rm  = it - f * (ABR * ABC);
        int k   = rm / ABC;
        int col = rm - k * ABC;
        int lr = jbase + k; if (lr > LRH - 1) lr = LRH - 1;
        int gx = ixbase + col; if (gx > LRW - 1) gx = LRW - 1;
        const float* __restrict__ src = f ? g_B : g_A;
        sAB[(f * ABR + k) * ABP + col] = src[(c * LRH + lr) * LRW + gx];
    }
    __syncthreads();

    // ---- Phase F2: sliding vertical pass with on-the-fly horizontal lerp ----
    if (tid < 136) {
        const int f  = tid >= 68 ? 1 : 0;
        const int qq = tid - f * 68;
        const float* __restrict__ Ab = &sAB[(f * ABR) * ABP];
        float* __restrict__ Sout = &sm[(f * SR) * SMP + qq * 2];
        float* __restrict__ Uout = &sm[UOFF + (f * UR) * SMP + qq * 2];

        const int   i0  = s_cix[2 * qq],     i1  = s_cix[2 * qq + 1];
        const float fx0 = s_cfx[2 * qq],     fx1 = s_cfx[2 * qq + 1];
        const float ofx0 = 1.0f - fx0,       ofx1 = 1.0f - fx1;

        float2 h0, h1;
        {
            const float* rw0 = Ab;           // k = 0
            h0.x = rw0[i0] * ofx0 + rw0[i0 + 1] * fx0;
            h0.y = rw0[i1] * ofx1 + rw0[i1 + 1] * fx1;
            const float* rw1 = Ab + ABP;     // k = 1
            h1.x = rw1[i0] * ofx0 + rw1[i0 + 1] * fx0;
            h1.y = rw1[i1] * ofx1 + rw1[i1 + 1] * fx1;
        }
        int kcur = 0;
        float2 ring[5];
#pragma unroll
        for (int e = 0; e < EXR; ++e) {
            int ke = s_ek[e];
            if (ke != kcur) {                // advances by exactly 1
                h0 = h1;
                const float* rw1 = Ab + (ke + 1) * ABP;
                h1.x = rw1[i0] * ofx0 + rw1[i0 + 1] * fx0;
                h1.y = rw1[i1] * ofx1 + rw1[i1 + 1] * fx1;
                kcur = ke;
            }
            float fy = s_efy[e], ofy = 1.0f - fy;
            float2 u;
            u.x = h0.x * ofy + h1.x * fy;
            u.y = h0.y * ofy + h1.y * fy;
            ring[e % 5] = u;
            if (e >= 4) {
                float2 s;
                s.x = ring[0].x + ring[1].x + ring[2].x + ring[3].x + ring[4].x;
                s.y = ring[0].y + ring[1].y + ring[2].y + ring[3].y + ring[4].y;
                *reinterpret_cast<float2*>(Sout + (e - 4) * SMP) = s;
                if (e < 4 + UR)
                    *reinterpret_cast<float2*>(Uout + (e - 4) * SMP) = u;
            }
        }
    }
    __syncthreads();

    // ---- Phase 3: one row per thread, eager P-folding ----
    const float imv[4] = {im4.x, im4.y, im4.z, im4.w};

    float Ptl[4], Ptr[4], Ptc[4];
    fold_row(&sm[(0 * SR + row) * SMP + xl], &sm[(1 * SR + row) * SMP + xl],
             imv, Ptl, Ptr, Ptc);

    float Pbl[4], Pbr[4], Pbc[4];
    fold_row(&sm[(0 * SR + row + 4) * SMP + xl], &sm[(1 * SR + row + 4) * SMP + xl],
             imv, Pbl, Pbr, Pbc);

    float Pcl[4], Pcr[4];
    {
        float vA[12], hA[8], vB[12], hB[8];
        load12(vA, &sm[UOFF + (0 * UR + row) * SMP + xl]); hsum5(hA, vA);
        load12(vB, &sm[UOFF + (1 * UR + row) * SMP + xl]); hsum5(hB, vB);
#pragma unroll
        for (int p = 0; p < 4; ++p) {
            Pcl[p] = fmaf(hA[p],     imv[p], hB[p]);
            Pcr[p] = fmaf(hA[p + 4], imv[p], hB[p + 4]);
        }
    }

    const float i45 = 1.0f / 45.0f, i25 = 1.0f / 25.0f;
    float res[4];
#pragma unroll
    for (int p = 0; p < 4; ++p) {
        const float im = imv[p];
        float d0 = fmaf(Ptl[p] + Pbl[p] - Pcl[p], i45, -im);  // L
        float d1 = fmaf(Ptr[p] + Pbr[p] - Pcr[p], i45, -im);  // R
        float d2 = fmaf(Ptl[p] + Ptr[p] - Ptc[p], i45, -im);  // U
        float d3 = fmaf(Pbl[p] + Pbr[p] - Pbc[p], i45, -im);  // D
        float d4 = fmaf(Ptl[p], i25, -im);                    // NW
        float d5 = fmaf(Ptr[p], i25, -im);                    // NE
        float d6 = fmaf(Pbl[p], i25, -im);                    // SW
        float d7 = fmaf(Pbr[p], i25, -im);                    // SE

        float bestA = fminf(fminf(fminf(fabsf(d0), fabsf(d1)),
                                  fminf(fabsf(d2), fabsf(d3))),
                            fminf(fminf(fabsf(d4), fabsf(d5)),
                                  fminf(fabsf(d6), fabsf(d7))));
        float best = d7;
        if (fabsf(d6) == bestA) best = d6;
        if (fabsf(d5) == bestA) best = d5;
        if (fabsf(d4) == bestA) best = d4;
        if (fabsf(d3) == bestA) best = d3;
        if (fabsf(d2) == bestA) best = d2;
        if (fabsf(d1) == bestA) best = d1;
        if (fabsf(d0) == bestA) best = d0;

        float r = truncf(best + im);
        res[p] = fminf(fmaxf(r, 0.0f), 255.0f);
    }
    *reinterpret_cast<float4*>(&out[(c * HRH + Y0 + row) * HRW + X0 + xl]) =
        make_float4(res[0], res[1], res[2], res[3]);
}

// ---------------------------------------------------------------------------
extern "C" void kernel_launch(void* const* d_in, const int* in_sizes, int n_in,
                              void* d_out, int out_size) {
    const float* lrx  = (const float*)d_in[0];
    const float* lry  = (const float*)d_in[1];
    const float* hrx  = (const float*)d_in[2];
    const float* boxw = (const float*)d_in[3];
    float* out = (float*)d_out;

    dim3 lgrid(LRW / LTS, LRH / LTS, NC);
    lr_fused<<<lgrid, 256>>>(lrx, lry, boxw);

    dim3 grid(HRW / XT, HRH / YS, NC);
    hr_fused<<<grid, HTHREADS>>>(hrx, out);
}

// round 16
// speedup vs baseline: 1.1404x; 1.1404x over previous
#include <cuda_runtime.h>
#include <math.h>

#define LRW 256
#define LRH 256
#define HRW 1024
#define HRH 1024
#define NC 3
#define RAD 4

#define LRN (NC * LRH * LRW)
#define SC (255.0f / 1023.0f)

// Scratch (no cudaMalloc allowed) — device globals.
__device__ float g_A[LRN];
__device__ float g_B[LRN];

// ---------------------------------------------------------------------------
// Helpers
// ---------------------------------------------------------------------------
__device__ __forceinline__ void load12(float* v, const float* base) {
    float4 q0 = *reinterpret_cast<const float4*>(base);
    float4 q1 = *reinterpret_cast<const float4*>(base + 4);
    float4 q2 = *reinterpret_cast<const float4*>(base + 8);
    v[0]=q0.x; v[1]=q0.y; v[2]=q0.z;  v[3]=q0.w;
    v[4]=q1.x; v[5]=q1.y; v[6]=q1.z;  v[7]=q1.w;
    v[8]=q2.x; v[9]=q2.y; v[10]=q2.z; v[11]=q2.w;
}

// h[i] = sum v[i..i+4], i = 0..7  (sliding 5-window)
__device__ __forceinline__ void hsum5(float* h, const float* v) {
    h[0] = v[0] + v[1] + v[2] + v[3] + v[4];
#pragma unroll
    for (int i = 1; i < 8; ++i) h[i] = h[i - 1] - v[i - 1] + v[i + 4];
}

// load S row, produce h sums + center cols (v[4..7])
__device__ __forceinline__ void loadrow(const float* base, float* h, float* cc) {
    float v[12];
    load12(v, base);
    hsum5(h, v);
    cc[0] = v[4]; cc[1] = v[5]; cc[2] = v[6]; cc[3] = v[7];
}

// ---------------------------------------------------------------------------
// Fused low-res kernel: tile 16x16 per block (grid 16x16x3), 256 threads.
// (round-14 version, unchanged)
// ---------------------------------------------------------------------------
#define LTS 16
#define LEX 24
#define LSP 28

__global__ void __launch_bounds__(256) lr_fused(const float* __restrict__ lrx,
                                                const float* __restrict__ lry,
                                                const float* __restrict__ boxw) {
    __shared__ __align__(16) float Xs[LEX * LSP];
    __shared__ __align__(16) float Ys[LEX * LSP];
    __shared__ __align__(16) float Vx[LTS * LSP];
    __shared__ __align__(16) float Vy[LTS * LSP];
    __shared__ __align__(16) float Vxy[LTS * LSP];
    __shared__ __align__(16) float Vxx[LTS * LSP];

    const int c = blockIdx.z;
    const int x0t = blockIdx.x * LTS;
    const int y0t = blockIdx.y * LTS;
    const int tid = threadIdx.x;
    const float* __restrict__ px = lrx + c * LRH * LRW;
    const float* __restrict__ py = lry + c * LRH * LRW;

    for (int j = tid; j < LEX * LEX; j += 256) {
        int ly = j / LEX, lx = j % LEX;
        int Y = y0t - RAD + ly; Y = Y < 0 ? 0 : (Y > LRH - 1 ? LRH - 1 : Y);
        int X = x0t - RAD + lx; X = X < 0 ? 0 : (X > LRW - 1 ? LRW - 1 : X);
        Xs[ly * LSP + lx] = px[Y * LRW + X];
        Ys[ly * LSP + lx] = py[Y * LRW + X];
    }
    __syncthreads();

    for (int j = tid; j < LTS * LEX; j += 256) {
        int ry = j / LEX, lx = j % LEX;
        float sx = 0.f, sy = 0.f, sxy = 0.f, sxx = 0.f;
#pragma unroll
        for (int k = 0; k < 9; ++k) {
            float vx = Xs[(ry + k) * LSP + lx];
            float vy = Ys[(ry + k) * LSP + lx];
            sx += vx; sy += vy; sxy += vx * vy; sxx += vx * vx;
        }
        Vx[ry * LSP + lx] = sx;  Vy[ry * LSP + lx] = sy;
        Vxy[ry * LSP + lx] = sxy; Vxx[ry * LSP + lx] = sxx;
    }
    __syncthreads();

    if (tid < 64) {
        const int ty = tid >> 2;            // 0..15
        const int x0 = (tid & 3) << 2;      // 0,4,8,12
        float vx[12], vy[12], vxy[12], vxx[12];
        load12(vx,  &Vx[ty * LSP + x0]);
        load12(vy,  &Vy[ty * LSP + x0]);
        load12(vxy, &Vxy[ty * LSP + x0]);
        load12(vxx, &Vxx[ty * LSP + x0]);

        float hx[4], hy[4], hxy[4], hxx[4];
        hx[0] = vx[0]+vx[1]+vx[2]+vx[3]+vx[4]+vx[5]+vx[6]+vx[7]+vx[8];
        hy[0] = vy[0]+vy[1]+vy[2]+vy[3]+vy[4]+vy[5]+vy[6]+vy[7]+vy[8];
        hxy[0]= vxy[0]+vxy[1]+vxy[2]+vxy[3]+vxy[4]+vxy[5]+vxy[6]+vxy[7]+vxy[8];
        hxx[0]= vxx[0]+vxx[1]+vxx[2]+vxx[3]+vxx[4]+vxx[5]+vxx[6]+vxx[7]+vxx[8];
#pragma unroll
        for (int i = 1; i < 4; ++i) {
            hx[i]  = hx[i-1]  - vx[i-1]  + vx[i+8];
            hy[i]  = hy[i-1]  - vy[i-1]  + vy[i+8];
            hxy[i] = hxy[i-1] - vxy[i-1] + vxy[i+8];
            hxx[i] = hxx[i-1] - vxx[i-1] + vxx[i+8];
        }

        const float w = boxw[c * 81];
        float A_[4], B_[4];
#pragma unroll
        for (int p = 0; p < 4; ++p) {
            float mx = hx[p] * w, my = hy[p] * w, mxy = hxy[p] * w, mxx = hxx[p] * w;
            float A = (mxy - mx * my) / (mxx - mx * mx + 2.0f);   // EPS = 2
            A_[p] = A; B_[p] = my - A * mx;
        }
        int o = c * LRH * LRW + (y0t + ty) * LRW + (x0t + x0);
        *reinterpret_cast<float4*>(&g_A[o]) = make_float4(A_[0], A_[1], A_[2], A_[3]);
        *reinterpret_cast<float4*>(&g_B[o]) = make_float4(B_[0], B_[1], B_[2], B_[3]);
    }
}

// ---------------------------------------------------------------------------
// HR fused: block = 128-col x 16-row tile (grid 8x64x3), 256 threads, (256,3).
// REVERTED to the proven round-13 structure (pairing), with ONE change:
// F2 is split into 3 overlapping row-groups x float4 width -> 204 active
// threads (was 136) and the serial dependent walk shrinks 24 -> 11 iters.
// Warm-up rows are recomputed, not emitted (values bit-identical).
// ---------------------------------------------------------------------------
#define XT 128
#define YS 16
#define SMP 140          // smem row stride (floats); 136 used
#define SR 20            // S rows: r in [Y0, Y0+19]
#define UR 16
#define EXR 24           // extended rows
#define UOFF (2 * SR * SMP)
#define ABR 10           // staged A/B LR rows
#define ABC 36           // staged A/B LR cols
#define ABP 37           // stride
#define PCOLS 136        // padded HR cols per block

// one output row of 4 px: top/bot S sums + centers, center-row U sums
__device__ __forceinline__ void emit_row(
    float* outp, const float4 im4,
    const float* hAt, const float* cAt, const float* hAb, const float* cAb,
    const float* hBt, const float* cBt, const float* hBb, const float* cBb,
    const float* hAc, const float* hBc)
{
    const float i45 = 1.0f / 45.0f, i25 = 1.0f / 25.0f;
    const float imv[4] = {im4.x, im4.y, im4.z, im4.w};
    float res[4];
#pragma unroll
    for (int p = 0; p < 4; ++p) {
        const float im = imv[p];
        float Ptl = fmaf(hAt[p],     im, hBt[p]);
        float Ptr = fmaf(hAt[p + 4], im, hBt[p + 4]);
        float Pbl = fmaf(hAb[p],     im, hBb[p]);
        float Pbr = fmaf(hAb[p + 4], im, hBb[p + 4]);
        float Pcl = fmaf(hAc[p],     im, hBc[p]);
        float Pcr = fmaf(hAc[p + 4], im, hBc[p + 4]);
        float Ptc = fmaf(cAt[p],     im, cBt[p]);
        float Pbc = fmaf(cAb[p],     im, cBb[p]);

        float d0 = fmaf(Ptl + Pbl - Pcl, i45, -im);  // L
        float d1 = fmaf(Ptr + Pbr - Pcr, i45, -im);  // R
        float d2 = fmaf(Ptl + Ptr - Ptc, i45, -im);  // U
        float d3 = fmaf(Pbl + Pbr - Pbc, i45, -im);  // D
        float d4 = fmaf(Ptl, i25, -im);              // NW
        float d5 = fmaf(Ptr, i25, -im);              // NE
        float d6 = fmaf(Pbl, i25, -im);              // SW
        float d7 = fmaf(Pbr, i25, -im);              // SE

        float bestA = fminf(fminf(fminf(fabsf(d0), fabsf(d1)),
                                  fminf(fabsf(d2), fabsf(d3))),
                            fminf(fminf(fabsf(d4), fabsf(d5)),
                                  fminf(fabsf(d6), fabsf(d7))));
        float best = d7;
        if (fabsf(d6) == bestA) best = d6;
        if (fabsf(d5) == bestA) best = d5;
        if (fabsf(d4) == bestA) best = d4;
        if (fabsf(d3) == bestA) best = d3;
        if (fabsf(d2) == bestA) best = d2;
        if (fabsf(d1) == bestA) best = d1;
        if (fabsf(d0) == bestA) best = d0;

        float r = truncf(best + im);
        res[p] = fminf(fmaxf(r, 0.0f), 255.0f);
    }
    *reinterpret_cast<float4*>(outp) = make_float4(res[0], res[1], res[2], res[3]);
}

__global__ void __launch_bounds__(256, 3) hr_fused(const float* __restrict__ hrx,
                                                   float* __restrict__ out) {
    __shared__ __align__(16) float sm[(2 * SR + 2 * UR) * SMP];   // 40.3 KB
    __shared__ __align__(16) float sAB[2 * ABR * ABP];            // 2.96 KB
    __shared__ int   s_ek[EXR];      // HL-row index rel. jbase per ext row
    __shared__ float s_efy[EXR];     // vertical lerp fraction per ext row
    __shared__ int   s_cix[PCOLS];   // LR col rel. ixbase per padded col
    __shared__ float s_cfx[PCOLS];   // horizontal lerp fraction per padded col

    const int c  = blockIdx.z;
    const int X0 = blockIdx.x * XT;
    const int Y0 = blockIdx.y * YS;
    const int tid = threadIdx.x;

    // block-uniform base LR row / col
    int Yb = Y0 - 4; Yb = Yb < 0 ? 0 : Yb;
    int jbase = (int)floorf((float)Yb * SC);
    if (jbase > LRH - 2) jbase = LRH - 2;
    int Xb = X0 - 4; Xb = Xb < 0 ? 0 : Xb;
    int ixbase = (int)floorf((float)Xb * SC);
    if (ixbase > LRW - 2) ixbase = LRW - 2;

    // ---- thread's pair mapping: rows r and r+4, 4-px column xl ----
    const int rw = tid >> 5;                       // 0..7
    const int xl = (tid & 31) << 2;                // 0..124
    const int r  = (rw & 3) + ((rw >> 2) << 3);    // 0..3, 8..11

    // ---- Prefetch hrx rows r and r+4 (latency hidden behind W/F0/F2) ----
    float4 im0 = *reinterpret_cast<const float4*>(
        &hrx[(c * HRH + Y0 + r) * HRW + X0 + xl]);
    float4 im1 = *reinterpret_cast<const float4*>(
        &hrx[(c * HRH + Y0 + r + 4) * HRW + X0 + xl]);

    // ---- Phase W: ext-row table + column table ----
    if (tid < EXR) {
        int Y = Y0 - 4 + tid; Y = Y < 0 ? 0 : (Y > HRH - 1 ? HRH - 1 : Y);
        float tt = (float)Y * SC;
        int iy = (int)floorf(tt); if (iy > LRH - 2) iy = LRH - 2;
        s_ek[tid]  = iy - jbase;
        s_efy[tid] = tt - (float)iy;
    } else if (tid >= 32 && tid < 32 + PCOLS) {
        int lx = tid - 32;
        int X = X0 - 4 + lx; X = X < 0 ? 0 : (X > HRW - 1 ? HRW - 1 : X);
        float tt = (float)X * SC;
        int ix = (int)floorf(tt); if (ix > LRW - 2) ix = LRW - 2;
        s_cix[lx] = ix - ixbase;           // 0..34; +1 <= 35 < ABC
        s_cfx[lx] = tt - (float)ix;
    }

    // ---- Phase F0: stage raw A,B sub-tile (coalesced scalar loads) ----
    for (int it = tid; it < 2 * ABR * ABC; it += 256) {
        int f   = it / (ABR * ABC);
        int rm  = it - f * (ABR * ABC);
        int k   = rm / ABC;
        int col = rm - k * ABC;
        int lr = jbase + k; if (lr > LRH - 1) lr = LRH - 1;
        int gx = ixbase + col; if (gx > LRW - 1) gx = LRW - 1;
        const float* __restrict__ src = f ? g_B : g_A;
        sAB[(f * ABR + k) * ABP + col] = src[(c * LRH + lr) * LRW + gx];
    }
    __syncthreads();

    // ---- Phase F2: 3 overlapping row-groups x float4 width.
    // Group g emits S rows [7g, 7g+6] (g2: 14..19) and U rows in range;
    // walks ext rows [7g, 7g+10] (g2: 14..23). 204 threads active.
    if (tid < 204) {
        const int g   = tid / 68;            // 0..2
        const int rem = tid - g * 68;
        const int f   = rem / 34;            // field
        const int q   = rem - f * 34;        // float4 quad 0..33
        const float* __restrict__ Ab = &sAB[(f * ABR) * ABP];
        float* __restrict__ Sout = &sm[(f * SR) * SMP + q * 4];
        float* __restrict__ Uout = &sm[UOFF + (f * UR) * SMP + q * 4];

        int   ci[4];
        float cf[4], co[4];
#pragma unroll
        for (int p = 0; p < 4; ++p) {
            ci[p] = s_cix[4 * q + p];
            cf[p] = s_cfx[4 * q + p];
            co[p] = 1.0f - cf[p];
        }

        const int e0 = 7 * g;
        int kcur = s_ek[e0];
        float h0[4], h1[4];
        {
            const float* r0 = Ab + kcur * ABP;
            const float* r1 = Ab + (kcur + 1) * ABP;
#pragma unroll
            for (int p = 0; p < 4; ++p) {
                h0[p] = r0[ci[p]] * co[p] + r0[ci[p] + 1] * cf[p];
                h1[p] = r1[ci[p]] * co[p] + r1[ci[p] + 1] * cf[p];
            }
        }
        float ring[5][4];
#pragma unroll
        for (int er = 0; er < 11; ++er) {
            int e = e0 + er;
            if (e <= 23) {                       // g2 skips er=10
                int ke = s_ek[e];
                if (ke != kcur) {                // advances by exactly 1
                    const float* r1 = Ab + (ke + 1) * ABP;
#pragma unroll
                    for (int p = 0; p < 4; ++p) {
                        h0[p] = h1[p];
                        h1[p] = r1[ci[p]] * co[p] + r1[ci[p] + 1] * cf[p];
                    }
                    kcur = ke;
                }
                float fy = s_efy[e], ofy = 1.0f - fy;
                float u[4];
#pragma unroll
                for (int p = 0; p < 4; ++p) {
                    u[p] = h0[p] * ofy + h1[p] * fy;
                    ring[er % 5][p] = u[p];
                }
                if (er >= 4) {
                    int sr = e - 4;                  // S row in [7g, ...]
                    float s[4];
#pragma unroll
                    for (int p = 0; p < 4; ++p)
                        s[p] = ring[0][p] + ring[1][p] + ring[2][p] +
                               ring[3][p] + ring[4][p];
                    *reinterpret_cast<float4*>(Sout + sr * SMP) =
                        make_float4(s[0], s[1], s[2], s[3]);
                    if (sr < UR)
                        *reinterpret_cast<float4*>(Uout + sr * SMP) =
                            make_float4(u[0], u[1], u[2], u[3]);
                }
            }
        }
    }
    __syncthreads();

    // ---- Phase 3: paired rows r, r+4 (byte-identical to round 13) ----
    float hAt[8], cAt[4], hAm[8], cAm[4];
    float hBt[8], cBt[4], hBm[8], cBm[4];
    loadrow(&sm[(0 * SR + r) * SMP + xl],     hAt, cAt);
    loadrow(&sm[(0 * SR + r + 4) * SMP + xl], hAm, cAm);
    loadrow(&sm[(1 * SR + r) * SMP + xl],     hBt, cBt);
    loadrow(&sm[(1 * SR + r + 4) * SMP + xl], hBm, cBm);

    // row r: top=(hAt,cAt), bot=(hAm,cAm)
    {
        float vAc[12], vBc[12], hAc[8], hBc[8];
        load12(vAc, &sm[UOFF + (0 * UR + r) * SMP + xl]); hsum5(hAc, vAc);
        load12(vBc, &sm[UOFF + (1 * UR + r) * SMP + xl]); hsum5(hBc, vBc);
        emit_row(&out[(c * HRH + Y0 + r) * HRW + X0 + xl], im0,
                 hAt, cAt, hAm, cAm, hBt, cBt, hBm, cBm, hAc, hBc);
    }

    // row r+4: top=(hAm,cAm), bot=S[r+8]
    {
        float hAb[8], cAb[4], hBb[8], cBb[4];
        loadrow(&sm[(0 * SR + r + 8) * SMP + xl], hAb, cAb);
        loadrow(&sm[(1 * SR + r + 8) * SMP + xl], hBb, cBb);
        float vAc[12], vBc[12], hAc[8], hBc[8];
        load12(vAc, &sm[UOFF + (0 * UR + r + 4) * SMP + xl]); hsum5(hAc, vAc);
        load12(vBc, &sm[UOFF + (1 * UR + r + 4) * SMP + xl]); hsum5(hBc, vBc);
        emit_row(&out[(c * HRH + Y0 + r + 4) * HRW + X0 + xl], im1,
                 hAm, cAm, hAb, cAb, hBm, cBm, hBb, cBb, hAc, hBc);
    }
}

// ---------------------------------------------------------------------------
extern "C" void kernel_launch(void* const* d_in, const int* in_sizes, int n_in,
                              void* d_out, int out_size) {
    const float* lrx  = (const float*)d_in[0];
    const float* lry  = (const float*)d_in[1];
    const float* hrx  = (const float*)d_in[2];
    const float* boxw = (const float*)d_in[3];
    float* out = (float*)d_out;

    dim3 lgrid(LRW / LTS, LRH / LTS, NC);
    lr_fused<<<lgrid, 256>>>(lrx, lry, boxw);

    dim3 grid(HRW / XT, HRH / YS, NC);
    hr_fused<<<grid, 256>>>(hrx, out);
}